// round 13
// baseline (speedup 1.0000x reference)
#include <cuda_runtime.h>

#define NN 100000
#define EE 1600000

// Scratch (allocation-free rule: __device__ globals)
__device__ float g_kw  [NN * 128];  // interleaved: [n][0:64]=k row, [n][64:128]=hw row
__device__ float g_q   [NN * 64];
__device__ int   g_cnt [NN];
__device__ int   g_roff[NN + 1];
__device__ int   g_cur [NN];
__device__ int   g_bsum[512];
__device__ int   g_esrc[EE];

// ---- tf32 helpers ----------------------------------------------------------
__device__ __forceinline__ unsigned to_tf32(float x)
{
    unsigned r; asm("cvt.rna.tf32.f32 %0, %1;" : "=r"(r) : "f"(x)); return r;
}
__device__ __forceinline__ void mma_tf32(float4& d, const unsigned* a, const unsigned* b)
{
    asm volatile(
        "mma.sync.aligned.m16n8k8.row.col.f32.tf32.tf32.f32 "
        "{%0,%1,%2,%3}, {%4,%5,%6,%7}, {%8,%9}, {%0,%1,%2,%3};"
        : "+f"(d.x), "+f"(d.y), "+f"(d.z), "+f"(d.w)
        : "r"(a[0]), "r"(a[1]), "r"(a[2]), "r"(a[3]), "r"(b[0]), "r"(b[1]));
}

// ---------------------------------------------------------------------------
// k = h@Wk, q = h@Wq, hw = h@W via 3xTF32 tensor-core MMA (fp32-class
// accuracy via hi/lo split). Runs on the SIDE stream, overlapped with the CSR
// chain. 192 threads = 6 warps = 3 matrices x 2 m-halves. (R10-12-proven.)
// ---------------------------------------------------------------------------
__global__ __launch_bounds__(192) void gemm_mma_kernel(
    const float* __restrict__ h,
    const float* __restrict__ Wk,
    const float* __restrict__ Wq,
    const float* __restrict__ Ww,
    int N)
{
    __shared__ float sA[32 * 72];        // sA[node][kdim]
    __shared__ float sW[3 * 64 * 72];    // sW[sel][kdim][col]

    const int tid = threadIdx.x;

    for (int idx = tid; idx < 64 * 64; idx += 192) {
        const int i = idx >> 6, c = idx & 63;
        sW[0 * 64 * 72 + i * 72 + c] = Wk[idx];
        sW[1 * 64 * 72 + i * 72 + c] = Wq[idx];
        sW[2 * 64 * 72 + i * 72 + c] = Ww[idx];
    }
    const int base = blockIdx.x * 32;
    for (int idx = tid; idx < 32 * 64; idx += 192) {
        const int n = idx >> 6, c = idx & 63;
        const int gn = base + n;
        sA[n * 72 + c] = (gn < N) ? h[(size_t)gn * 64 + c] : 0.f;
    }
    __syncthreads();

    const int wid  = tid >> 5;
    const int lane = tid & 31;
    const int sel  = wid >> 1;          // 0:Wk 1:Wq 2:Ww
    const int mh   = wid & 1;           // m-half (16 nodes)
    const int g    = lane >> 2;         // 0..7
    const int t4   = lane & 3;          // 0..3

    float4 acc[8];
#pragma unroll
    for (int nt = 0; nt < 8; nt++) acc[nt] = make_float4(0.f, 0.f, 0.f, 0.f);

    const float* wm = sW + sel * 64 * 72;

#pragma unroll
    for (int ks = 0; ks < 8; ks++) {
        const int r0 = (mh * 16 + g) * 72 + ks * 8 + t4;
        const int r1 = (mh * 16 + g + 8) * 72 + ks * 8 + t4;
        const float a0f = sA[r0],     a1f = sA[r1];
        const float a2f = sA[r0 + 4], a3f = sA[r1 + 4];

        unsigned ahi[4], alo[4];
        ahi[0] = to_tf32(a0f); alo[0] = to_tf32(a0f - __uint_as_float(ahi[0]));
        ahi[1] = to_tf32(a1f); alo[1] = to_tf32(a1f - __uint_as_float(ahi[1]));
        ahi[2] = to_tf32(a2f); alo[2] = to_tf32(a2f - __uint_as_float(ahi[2]));
        ahi[3] = to_tf32(a3f); alo[3] = to_tf32(a3f - __uint_as_float(ahi[3]));

#pragma unroll
        for (int nt = 0; nt < 8; nt++) {
            const float b0f = wm[(ks * 8 + t4) * 72 + nt * 8 + g];
            const float b1f = wm[(ks * 8 + t4 + 4) * 72 + nt * 8 + g];
            unsigned bhi[2], blo[2];
            bhi[0] = to_tf32(b0f); blo[0] = to_tf32(b0f - __uint_as_float(bhi[0]));
            bhi[1] = to_tf32(b1f); blo[1] = to_tf32(b1f - __uint_as_float(bhi[1]));

            mma_tf32(acc[nt], ahi, bhi);
            mma_tf32(acc[nt], ahi, blo);
            mma_tf32(acc[nt], alo, bhi);
        }
    }

    const int gn0 = base + mh * 16 + g;
    const int gn1 = gn0 + 8;
#pragma unroll
    for (int nt = 0; nt < 8; nt++) {
        const int col = nt * 8 + t4 * 2;
        if (sel == 0) {
            if (gn0 < N) *(float2*)&g_kw[(size_t)gn0 * 128 + col] = make_float2(acc[nt].x, acc[nt].y);
            if (gn1 < N) *(float2*)&g_kw[(size_t)gn1 * 128 + col] = make_float2(acc[nt].z, acc[nt].w);
        } else if (sel == 1) {
            if (gn0 < N) *(float2*)&g_q[(size_t)gn0 * 64 + col] = make_float2(acc[nt].x, acc[nt].y);
            if (gn1 < N) *(float2*)&g_q[(size_t)gn1 * 64 + col] = make_float2(acc[nt].z, acc[nt].w);
        } else {
            if (gn0 < N) *(float2*)&g_kw[(size_t)gn0 * 128 + 64 + col] = make_float2(acc[nt].x, acc[nt].y);
            if (gn1 < N) *(float2*)&g_kw[(size_t)gn1 * 128 + 64 + col] = make_float2(acc[nt].z, acc[nt].w);
        }
    }
}

// ---------------------------------------------------------------------------
// Histogram of dst (int4 loads)
// ---------------------------------------------------------------------------
__global__ void hist_kernel(const int* __restrict__ dst, int E)
{
    const int i4 = (blockIdx.x * blockDim.x + threadIdx.x) * 4;
    if (i4 + 3 < E) {
        const int4 d = *(const int4*)(dst + i4);
        atomicAdd(&g_cnt[d.x], 1);
        atomicAdd(&g_cnt[d.y], 1);
        atomicAdd(&g_cnt[d.z], 1);
        atomicAdd(&g_cnt[d.w], 1);
    } else {
        for (int j = i4; j < E; j++) atomicAdd(&g_cnt[dst[j]], 1);
    }
}

// ---------------------------------------------------------------------------
// Scan stage 1: per-block exclusive scan + block totals (no spinning).
// ---------------------------------------------------------------------------
__global__ __launch_bounds__(256) void scan1_kernel(int N)
{
    __shared__ int wsum[8];
    const int t = threadIdx.x, lane = t & 31, wd = t >> 5;
    const int i = blockIdx.x * 256 + t;
    const int v = (i < N) ? g_cnt[i] : 0;
    int x = v;
#pragma unroll
    for (int off = 1; off < 32; off <<= 1) {
        int y = __shfl_up_sync(0xffffffffu, x, off);
        if (lane >= off) x += y;
    }
    if (lane == 31) wsum[wd] = x;
    __syncthreads();
    if (t < 8) {
        int w = wsum[t];
        int xs = w;
#pragma unroll
        for (int off = 1; off < 8; off <<= 1) {
            int y = __shfl_up_sync(0x000000ffu, xs, off);
            if (t >= off) xs += y;
        }
        wsum[t] = xs - w;                       // exclusive warp offset
        if (t == 7) g_bsum[blockIdx.x] = xs;    // block total
    }
    __syncthreads();
    if (i < N) g_roff[i] = x - v + wsum[wd];
}

// ---------------------------------------------------------------------------
// Scan stage 2+3 merged: each block recomputes its block-prefix from g_bsum
// (block reduce over < nb ints — cheap, redundant, spin-free), then applies.
// ---------------------------------------------------------------------------
__global__ __launch_bounds__(256) void scan23_kernel(int N, int E, int nb)
{
    __shared__ int wred[8];
    const int t = threadIdx.x, lane = t & 31, wd = t >> 5;
    const int bid = blockIdx.x;

    int acc = 0;
    for (int j = t; j < bid; j += 256) acc += g_bsum[j];
#pragma unroll
    for (int off = 16; off > 0; off >>= 1)
        acc += __shfl_xor_sync(0xffffffffu, acc, off);
    if (lane == 0) wred[wd] = acc;
    __syncthreads();
    if (t == 0) {
        int s = 0;
#pragma unroll
        for (int j = 0; j < 8; j++) s += wred[j];
        wred[0] = s;
    }
    __syncthreads();
    const int boff = wred[0];

    const int i = bid * 256 + t;
    if (i < N) {
        const int r = g_roff[i] + boff;
        g_roff[i] = r;
        g_cur[i]  = r;
    }
    if (bid == 0 && t == 0) g_roff[N] = E;
}

// ---------------------------------------------------------------------------
// Scatter src ids into CSR order (int4 loads)
// ---------------------------------------------------------------------------
__global__ void scatter_kernel(const int* __restrict__ src,
                               const int* __restrict__ dst, int E)
{
    const int i4 = (blockIdx.x * blockDim.x + threadIdx.x) * 4;
    if (i4 + 3 < E) {
        const int4 d = *(const int4*)(dst + i4);
        const int4 s = *(const int4*)(src + i4);
        g_esrc[atomicAdd(&g_cur[d.x], 1)] = s.x;
        g_esrc[atomicAdd(&g_cur[d.y], 1)] = s.y;
        g_esrc[atomicAdd(&g_cur[d.z], 1)] = s.z;
        g_esrc[atomicAdd(&g_cur[d.w], 1)] = s.w;
    } else {
        for (int j = i4; j < E; j++)
            g_esrc[atomicAdd(&g_cur[dst[j]], 1)] = src[j];
    }
}

// ---------------------------------------------------------------------------
// Fused edge-softmax + aggregation. One warp per destination node; lean
// consumption (lane l owns features 2l..2l+1; own head hh = l>>3; 3-xor dot
// reduce; 3 relative xor shuffles for other heads; z recovered after the
// loop). FOUR-wide software pipeline: 4 edges resident + 4 prefetching ->
// up to 12 independent LDG.64s in flight per lane. Remainder edges are
// already resident from the last prefetch (no extra loads in the tail).
// ---------------------------------------------------------------------------
__global__ __launch_bounds__(256) void gather_kernel(
    const float* __restrict__ b,
    float* __restrict__ out,
    int N)
{
    const int n    = (blockIdx.x * 256 + threadIdx.x) >> 5;
    const int lane = threadIdx.x & 31;
    if (n >= N) return;
    const int hh = lane >> 3;   // own head

    const float2 q2 = ((const float2*)(g_q + (size_t)n * 64))[lane];
    const int p0 = g_roff[n];
    const int p1 = g_roff[n + 1];

    float2 a0 = make_float2(0.f, 0.f), a1 = a0, a2 = a0, a3 = a0;
    float z0 = 0.f;

#define GK_LOAD(kk, ww, sid)                                              \
    do {                                                                  \
        const float2* _kp = (const float2*)(g_kw + (size_t)(sid) * 128);  \
        kk = _kp[lane];                                                   \
        ww = _kp[lane + 32];                                              \
    } while (0)

#define GK_CONSUME(kk, ww)                                                \
    do {                                                                  \
        float prod = kk.x * q2.x + kk.y * q2.y;                           \
        prod += __shfl_xor_sync(0xffffffffu, prod, 4);                    \
        prod += __shfl_xor_sync(0xffffffffu, prod, 2);                    \
        prod += __shfl_xor_sync(0xffffffffu, prod, 1);                    \
        const float ew = __expf(prod);                                    \
        const float eA = __shfl_xor_sync(0xffffffffu, ew, 8);             \
        const float eB = __shfl_xor_sync(0xffffffffu, ew, 16);            \
        const float eC = __shfl_xor_sync(0xffffffffu, ew, 24);            \
        z0 += ew;                                                         \
        a0.x += ew * ww.x; a0.y += ew * ww.y;                             \
        a1.x += eA * ww.x; a1.y += eA * ww.y;                             \
        a2.x += eB * ww.x; a2.y += eB * ww.y;                             \
        a3.x += eC * ww.x; a3.y += eC * ww.y;                             \
    } while (0)

    if (p0 < p1) {
        float2 ka, wa, kb, wb, kc, wc, kd, wd;
        GK_LOAD(ka, wa, g_esrc[p0]);
        if (p0 + 1 < p1) GK_LOAD(kb, wb, g_esrc[p0 + 1]);
        if (p0 + 2 < p1) GK_LOAD(kc, wc, g_esrc[p0 + 2]);
        if (p0 + 3 < p1) GK_LOAD(kd, wd, g_esrc[p0 + 3]);

        int p = p0;
        for (; p + 3 < p1; p += 4) {
            float2 n0k = ka, n0w = wa, n1k = kb, n1w = wb;
            float2 n2k = kc, n2w = wc, n3k = kd, n3w = wd;
            if (p + 4 < p1) GK_LOAD(n0k, n0w, g_esrc[p + 4]);
            if (p + 5 < p1) GK_LOAD(n1k, n1w, g_esrc[p + 5]);
            if (p + 6 < p1) GK_LOAD(n2k, n2w, g_esrc[p + 6]);
            if (p + 7 < p1) GK_LOAD(n3k, n3w, g_esrc[p + 7]);

            GK_CONSUME(ka, wa);
            GK_CONSUME(kb, wb);
            GK_CONSUME(kc, wc);
            GK_CONSUME(kd, wd);

            ka = n0k; wa = n0w; kb = n1k; wb = n1w;
            kc = n2k; wc = n2w; kd = n3k; wd = n3w;
        }
        // remainder (0..3 edges) — already resident in ka..kc
        if (p     < p1) GK_CONSUME(ka, wa);
        if (p + 1 < p1) GK_CONSUME(kb, wb);
        if (p + 2 < p1) GK_CONSUME(kc, wc);
    }
#undef GK_LOAD
#undef GK_CONSUME

    // other heads' z from own-head lanes
    const float z1 = __shfl_xor_sync(0xffffffffu, z0, 8);
    const float z2 = __shfl_xor_sync(0xffffffffu, z0, 16);
    const float z3 = __shfl_xor_sync(0xffffffffu, z0, 24);

    const float i0 = (z0 > 0.f) ? 1.f / z0 : 0.f;
    const float i1 = (z1 > 0.f) ? 1.f / z1 : 0.f;
    const float i2 = (z2 > 0.f) ? 1.f / z2 : 0.f;
    const float i3 = (z3 > 0.f) ? 1.f / z3 : 0.f;

    const float2 bb = ((const float2*)b)[lane];   // features 2l, 2l+1
    float* op = out + (size_t)n * 256 + 2 * lane;

    *(float2*)(op + (size_t)(hh     ) * 64) = make_float2(a0.x * i0 + bb.x, a0.y * i0 + bb.y);
    *(float2*)(op + (size_t)(hh ^ 1) * 64) = make_float2(a1.x * i1 + bb.x, a1.y * i1 + bb.y);
    *(float2*)(op + (size_t)(hh ^ 2) * 64) = make_float2(a2.x * i2 + bb.x, a2.y * i2 + bb.y);
    *(float2*)(op + (size_t)(hh ^ 3) * 64) = make_float2(a3.x * i3 + bb.x, a3.y * i3 + bb.y);
}

// ---------------------------------------------------------------------------
extern "C" void kernel_launch(void* const* d_in, const int* in_sizes, int n_in,
                              void* d_out, int out_size)
{
    const float* h   = (const float*)d_in[0];
    const int*   src = (const int*)  d_in[1];
    const int*   dst = (const int*)  d_in[2];
    const float* Wk  = (const float*)d_in[3];
    const float* Wq  = (const float*)d_in[4];
    const float* Ww  = (const float*)d_in[5];
    const float* b   = (const float*)d_in[6];
    float*       out = (float*)d_out;

    const int N  = in_sizes[0] / 64;
    const int E  = in_sizes[1];
    const int nb = (N + 255) / 256;

    static void* cnt_ptr = nullptr;
    static cudaStream_t sideStream = nullptr;
    static cudaEvent_t  evFork = nullptr, evJoin = nullptr;
    if (cnt_ptr == nullptr) {
        cudaGetSymbolAddress(&cnt_ptr, g_cnt);
        cudaStreamCreateWithFlags(&sideStream, cudaStreamNonBlocking);
        cudaEventCreateWithFlags(&evFork, cudaEventDisableTiming);
        cudaEventCreateWithFlags(&evJoin, cudaEventDisableTiming);
    }

    // Fork: pure gemm (h,W only) overlaps the whole CSR chain (src,dst only).
    cudaEventRecord(evFork, 0);
    cudaStreamWaitEvent(sideStream, evFork, 0);
    gemm_mma_kernel<<<(N + 31) / 32, 192, 0, sideStream>>>(h, Wk, Wq, Ww, N);
    cudaEventRecord(evJoin, sideStream);

    cudaMemsetAsync(cnt_ptr, 0, (size_t)N * sizeof(int));
    hist_kernel<<<(E / 4 + 255) / 256, 256>>>(dst, E);
    scan1_kernel<<<nb, 256>>>(N);
    scan23_kernel<<<nb, 256>>>(N, E, nb);
    scatter_kernel<<<(E / 4 + 255) / 256, 256>>>(src, dst, E);

    cudaStreamWaitEvent(0, evJoin, 0);
    gather_kernel<<<(N + 7) / 8, 256>>>(b, out, N);
}

// round 14
// speedup vs baseline: 1.0372x; 1.0372x over previous
#include <cuda_runtime.h>

#define NN 100000
#define EE 1600000

// Scratch (allocation-free rule: __device__ globals)
__device__ float g_kw  [NN * 128];  // interleaved: [n][0:64]=k row, [n][64:128]=hw row
__device__ float g_q   [NN * 64];
__device__ int   g_cnt [NN];
__device__ int   g_roff[NN + 1];
__device__ int   g_cur [NN];
__device__ int   g_bsum[512];
__device__ int   g_esrc[EE];

// ---- tf32 helpers ----------------------------------------------------------
__device__ __forceinline__ unsigned to_tf32(float x)
{
    unsigned r; asm("cvt.rna.tf32.f32 %0, %1;" : "=r"(r) : "f"(x)); return r;
}
__device__ __forceinline__ void mma_tf32(float4& d, const unsigned* a, const unsigned* b)
{
    asm volatile(
        "mma.sync.aligned.m16n8k8.row.col.f32.tf32.tf32.f32 "
        "{%0,%1,%2,%3}, {%4,%5,%6,%7}, {%8,%9}, {%0,%1,%2,%3};"
        : "+f"(d.x), "+f"(d.y), "+f"(d.z), "+f"(d.w)
        : "r"(a[0]), "r"(a[1]), "r"(a[2]), "r"(a[3]), "r"(b[0]), "r"(b[1]));
}

// ---------------------------------------------------------------------------
// k = h@Wk, q = h@Wq, hw = h@W via 3xTF32 tensor-core MMA (fp32-class
// accuracy via hi/lo split). Runs on the SIDE stream, overlapped with the CSR
// chain. 192 threads = 6 warps = 3 matrices x 2 m-halves. (R10-12-proven.)
// ---------------------------------------------------------------------------
__global__ __launch_bounds__(192) void gemm_mma_kernel(
    const float* __restrict__ h,
    const float* __restrict__ Wk,
    const float* __restrict__ Wq,
    const float* __restrict__ Ww,
    int N)
{
    __shared__ float sA[32 * 72];        // sA[node][kdim]
    __shared__ float sW[3 * 64 * 72];    // sW[sel][kdim][col]

    const int tid = threadIdx.x;

    for (int idx = tid; idx < 64 * 64; idx += 192) {
        const int i = idx >> 6, c = idx & 63;
        sW[0 * 64 * 72 + i * 72 + c] = Wk[idx];
        sW[1 * 64 * 72 + i * 72 + c] = Wq[idx];
        sW[2 * 64 * 72 + i * 72 + c] = Ww[idx];
    }
    const int base = blockIdx.x * 32;
    for (int idx = tid; idx < 32 * 64; idx += 192) {
        const int n = idx >> 6, c = idx & 63;
        const int gn = base + n;
        sA[n * 72 + c] = (gn < N) ? h[(size_t)gn * 64 + c] : 0.f;
    }
    __syncthreads();

    const int wid  = tid >> 5;
    const int lane = tid & 31;
    const int sel  = wid >> 1;          // 0:Wk 1:Wq 2:Ww
    const int mh   = wid & 1;           // m-half (16 nodes)
    const int g    = lane >> 2;         // 0..7
    const int t4   = lane & 3;          // 0..3

    float4 acc[8];
#pragma unroll
    for (int nt = 0; nt < 8; nt++) acc[nt] = make_float4(0.f, 0.f, 0.f, 0.f);

    const float* wm = sW + sel * 64 * 72;

#pragma unroll
    for (int ks = 0; ks < 8; ks++) {
        const int r0 = (mh * 16 + g) * 72 + ks * 8 + t4;
        const int r1 = (mh * 16 + g + 8) * 72 + ks * 8 + t4;
        const float a0f = sA[r0],     a1f = sA[r1];
        const float a2f = sA[r0 + 4], a3f = sA[r1 + 4];

        unsigned ahi[4], alo[4];
        ahi[0] = to_tf32(a0f); alo[0] = to_tf32(a0f - __uint_as_float(ahi[0]));
        ahi[1] = to_tf32(a1f); alo[1] = to_tf32(a1f - __uint_as_float(ahi[1]));
        ahi[2] = to_tf32(a2f); alo[2] = to_tf32(a2f - __uint_as_float(ahi[2]));
        ahi[3] = to_tf32(a3f); alo[3] = to_tf32(a3f - __uint_as_float(ahi[3]));

#pragma unroll
        for (int nt = 0; nt < 8; nt++) {
            const float b0f = wm[(ks * 8 + t4) * 72 + nt * 8 + g];
            const float b1f = wm[(ks * 8 + t4 + 4) * 72 + nt * 8 + g];
            unsigned bhi[2], blo[2];
            bhi[0] = to_tf32(b0f); blo[0] = to_tf32(b0f - __uint_as_float(bhi[0]));
            bhi[1] = to_tf32(b1f); blo[1] = to_tf32(b1f - __uint_as_float(bhi[1]));

            mma_tf32(acc[nt], ahi, bhi);
            mma_tf32(acc[nt], ahi, blo);
            mma_tf32(acc[nt], alo, bhi);
        }
    }

    const int gn0 = base + mh * 16 + g;
    const int gn1 = gn0 + 8;
#pragma unroll
    for (int nt = 0; nt < 8; nt++) {
        const int col = nt * 8 + t4 * 2;
        if (sel == 0) {
            if (gn0 < N) *(float2*)&g_kw[(size_t)gn0 * 128 + col] = make_float2(acc[nt].x, acc[nt].y);
            if (gn1 < N) *(float2*)&g_kw[(size_t)gn1 * 128 + col] = make_float2(acc[nt].z, acc[nt].w);
        } else if (sel == 1) {
            if (gn0 < N) *(float2*)&g_q[(size_t)gn0 * 64 + col] = make_float2(acc[nt].x, acc[nt].y);
            if (gn1 < N) *(float2*)&g_q[(size_t)gn1 * 64 + col] = make_float2(acc[nt].z, acc[nt].w);
        } else {
            if (gn0 < N) *(float2*)&g_kw[(size_t)gn0 * 128 + 64 + col] = make_float2(acc[nt].x, acc[nt].y);
            if (gn1 < N) *(float2*)&g_kw[(size_t)gn1 * 128 + 64 + col] = make_float2(acc[nt].z, acc[nt].w);
        }
    }
}

// ---------------------------------------------------------------------------
// Histogram of dst (int4 loads)
// ---------------------------------------------------------------------------
__global__ void hist_kernel(const int* __restrict__ dst, int E)
{
    const int i4 = (blockIdx.x * blockDim.x + threadIdx.x) * 4;
    if (i4 + 3 < E) {
        const int4 d = *(const int4*)(dst + i4);
        atomicAdd(&g_cnt[d.x], 1);
        atomicAdd(&g_cnt[d.y], 1);
        atomicAdd(&g_cnt[d.z], 1);
        atomicAdd(&g_cnt[d.w], 1);
    } else {
        for (int j = i4; j < E; j++) atomicAdd(&g_cnt[dst[j]], 1);
    }
}

// ---------------------------------------------------------------------------
// Scan stage 1: per-block exclusive scan + block totals (no spinning).
// ---------------------------------------------------------------------------
__global__ __launch_bounds__(256) void scan1_kernel(int N)
{
    __shared__ int wsum[8];
    const int t = threadIdx.x, lane = t & 31, wd = t >> 5;
    const int i = blockIdx.x * 256 + t;
    const int v = (i < N) ? g_cnt[i] : 0;
    int x = v;
#pragma unroll
    for (int off = 1; off < 32; off <<= 1) {
        int y = __shfl_up_sync(0xffffffffu, x, off);
        if (lane >= off) x += y;
    }
    if (lane == 31) wsum[wd] = x;
    __syncthreads();
    if (t < 8) {
        int w = wsum[t];
        int xs = w;
#pragma unroll
        for (int off = 1; off < 8; off <<= 1) {
            int y = __shfl_up_sync(0x000000ffu, xs, off);
            if (t >= off) xs += y;
        }
        wsum[t] = xs - w;                       // exclusive warp offset
        if (t == 7) g_bsum[blockIdx.x] = xs;    // block total
    }
    __syncthreads();
    if (i < N) g_roff[i] = x - v + wsum[wd];
}

// ---------------------------------------------------------------------------
// Scan stage 2+3 merged: each block recomputes its block-prefix from g_bsum
// (block reduce over < nb ints — cheap, redundant, spin-free), then applies.
// ---------------------------------------------------------------------------
__global__ __launch_bounds__(256) void scan23_kernel(int N, int E, int nb)
{
    __shared__ int wred[8];
    const int t = threadIdx.x, lane = t & 31, wd = t >> 5;
    const int bid = blockIdx.x;

    int acc = 0;
    for (int j = t; j < bid; j += 256) acc += g_bsum[j];
#pragma unroll
    for (int off = 16; off > 0; off >>= 1)
        acc += __shfl_xor_sync(0xffffffffu, acc, off);
    if (lane == 0) wred[wd] = acc;
    __syncthreads();
    if (t == 0) {
        int s = 0;
#pragma unroll
        for (int j = 0; j < 8; j++) s += wred[j];
        wred[0] = s;
    }
    __syncthreads();
    const int boff = wred[0];

    const int i = bid * 256 + t;
    if (i < N) {
        const int r = g_roff[i] + boff;
        g_roff[i] = r;
        g_cur[i]  = r;
    }
    if (bid == 0 && t == 0) g_roff[N] = E;
}

// ---------------------------------------------------------------------------
// Scatter src ids into CSR order (int4 loads)
// ---------------------------------------------------------------------------
__global__ void scatter_kernel(const int* __restrict__ src,
                               const int* __restrict__ dst, int E)
{
    const int i4 = (blockIdx.x * blockDim.x + threadIdx.x) * 4;
    if (i4 + 3 < E) {
        const int4 d = *(const int4*)(dst + i4);
        const int4 s = *(const int4*)(src + i4);
        g_esrc[atomicAdd(&g_cur[d.x], 1)] = s.x;
        g_esrc[atomicAdd(&g_cur[d.y], 1)] = s.y;
        g_esrc[atomicAdd(&g_cur[d.z], 1)] = s.z;
        g_esrc[atomicAdd(&g_cur[d.w], 1)] = s.w;
    } else {
        for (int j = i4; j < E; j++)
            g_esrc[atomicAdd(&g_cur[dst[j]], 1)] = src[j];
    }
}

// ---------------------------------------------------------------------------
// Fused edge-softmax + aggregation (R12-proven 2-deep pipeline) + L2 cache
// policy: esrc reads and out writes are STREAMING (evict-first, __ldcs/__stcs)
// so the reused k|hw and q rows stay L2-resident.
// ---------------------------------------------------------------------------
__global__ __launch_bounds__(256) void gather_kernel(
    const float* __restrict__ b,
    float* __restrict__ out,
    int N)
{
    const int n    = (blockIdx.x * 256 + threadIdx.x) >> 5;
    const int lane = threadIdx.x & 31;
    if (n >= N) return;
    const int hh = lane >> 3;   // own head

    const float2 q2 = ((const float2*)(g_q + (size_t)n * 64))[lane];
    const int p0 = g_roff[n];
    const int p1 = g_roff[n + 1];

    float2 a0 = make_float2(0.f, 0.f), a1 = a0, a2 = a0, a3 = a0;
    float z0 = 0.f;

#define GK_LOAD(kk, ww, sid)                                              \
    do {                                                                  \
        const float2* _kp = (const float2*)(g_kw + (size_t)(sid) * 128);  \
        kk = _kp[lane];                                                   \
        ww = _kp[lane + 32];                                              \
    } while (0)

#define GK_CONSUME(kk, ww)                                                \
    do {                                                                  \
        float prod = kk.x * q2.x + kk.y * q2.y;                           \
        prod += __shfl_xor_sync(0xffffffffu, prod, 4);                    \
        prod += __shfl_xor_sync(0xffffffffu, prod, 2);                    \
        prod += __shfl_xor_sync(0xffffffffu, prod, 1);                    \
        const float ew = __expf(prod);                                    \
        const float eA = __shfl_xor_sync(0xffffffffu, ew, 8);             \
        const float eB = __shfl_xor_sync(0xffffffffu, ew, 16);            \
        const float eC = __shfl_xor_sync(0xffffffffu, ew, 24);            \
        z0 += ew;                                                         \
        a0.x += ew * ww.x; a0.y += ew * ww.y;                             \
        a1.x += eA * ww.x; a1.y += eA * ww.y;                             \
        a2.x += eB * ww.x; a2.y += eB * ww.y;                             \
        a3.x += eC * ww.x; a3.y += eC * ww.y;                             \
    } while (0)

    if (p0 < p1) {
        float2 ka, wa, kb, wb;
        GK_LOAD(ka, wa, __ldcs(&g_esrc[p0]));
        if (p0 + 1 < p1) GK_LOAD(kb, wb, __ldcs(&g_esrc[p0 + 1]));

        int p = p0;
        for (; p + 1 < p1; p += 2) {
            float2 kn0 = ka, wn0 = wa, kn1 = kb, wn1 = wb;
            if (p + 2 < p1) GK_LOAD(kn0, wn0, __ldcs(&g_esrc[p + 2]));
            if (p + 3 < p1) GK_LOAD(kn1, wn1, __ldcs(&g_esrc[p + 3]));

            GK_CONSUME(ka, wa);
            GK_CONSUME(kb, wb);

            ka = kn0; wa = wn0; kb = kn1; wb = wn1;
        }
        if (p < p1) GK_CONSUME(ka, wa);
    }
#undef GK_LOAD
#undef GK_CONSUME

    // other heads' z from own-head lanes
    const float z1 = __shfl_xor_sync(0xffffffffu, z0, 8);
    const float z2 = __shfl_xor_sync(0xffffffffu, z0, 16);
    const float z3 = __shfl_xor_sync(0xffffffffu, z0, 24);

    const float i0 = (z0 > 0.f) ? 1.f / z0 : 0.f;
    const float i1 = (z1 > 0.f) ? 1.f / z1 : 0.f;
    const float i2 = (z2 > 0.f) ? 1.f / z2 : 0.f;
    const float i3 = (z3 > 0.f) ? 1.f / z3 : 0.f;

    const float2 bb = ((const float2*)b)[lane];   // features 2l, 2l+1
    float* op = out + (size_t)n * 256 + 2 * lane;

    __stcs((float2*)(op + (size_t)(hh     ) * 64),
           make_float2(a0.x * i0 + bb.x, a0.y * i0 + bb.y));
    __stcs((float2*)(op + (size_t)(hh ^ 1) * 64),
           make_float2(a1.x * i1 + bb.x, a1.y * i1 + bb.y));
    __stcs((float2*)(op + (size_t)(hh ^ 2) * 64),
           make_float2(a2.x * i2 + bb.x, a2.y * i2 + bb.y));
    __stcs((float2*)(op + (size_t)(hh ^ 3) * 64),
           make_float2(a3.x * i3 + bb.x, a3.y * i3 + bb.y));
}

// ---------------------------------------------------------------------------
extern "C" void kernel_launch(void* const* d_in, const int* in_sizes, int n_in,
                              void* d_out, int out_size)
{
    const float* h   = (const float*)d_in[0];
    const int*   src = (const int*)  d_in[1];
    const int*   dst = (const int*)  d_in[2];
    const float* Wk  = (const float*)d_in[3];
    const float* Wq  = (const float*)d_in[4];
    const float* Ww  = (const float*)d_in[5];
    const float* b   = (const float*)d_in[6];
    float*       out = (float*)d_out;

    const int N  = in_sizes[0] / 64;
    const int E  = in_sizes[1];
    const int nb = (N + 255) / 256;

    static void* cnt_ptr = nullptr;
    static cudaStream_t sideStream = nullptr;
    static cudaEvent_t  evFork = nullptr, evJoin = nullptr;
    if (cnt_ptr == nullptr) {
        cudaGetSymbolAddress(&cnt_ptr, g_cnt);
        cudaStreamCreateWithFlags(&sideStream, cudaStreamNonBlocking);
        cudaEventCreateWithFlags(&evFork, cudaEventDisableTiming);
        cudaEventCreateWithFlags(&evJoin, cudaEventDisableTiming);
    }

    // Fork: pure gemm (h,W only) overlaps the whole CSR chain (src,dst only).
    cudaEventRecord(evFork, 0);
    cudaStreamWaitEvent(sideStream, evFork, 0);
    gemm_mma_kernel<<<(N + 31) / 32, 192, 0, sideStream>>>(h, Wk, Wq, Ww, N);
    cudaEventRecord(evJoin, sideStream);

    cudaMemsetAsync(cnt_ptr, 0, (size_t)N * sizeof(int));
    hist_kernel<<<(E / 4 + 255) / 256, 256>>>(dst, E);
    scan1_kernel<<<nb, 256>>>(N);
    scan23_kernel<<<nb, 256>>>(N, E, nb);
    scatter_kernel<<<(E / 4 + 255) / 256, 256>>>(src, dst, E);

    cudaStreamWaitEvent(0, evJoin, 0);
    gather_kernel<<<(N + 7) / 8, 256>>>(b, out, N);
}

// round 15
// speedup vs baseline: 1.0764x; 1.0377x over previous
#include <cuda_runtime.h>

#define NN 100000
#define EE 1600000

// Scratch (allocation-free rule: __device__ globals)
__device__ float g_kw  [NN * 128];  // interleaved: [n][0:64]=k row, [n][64:128]=hw row
__device__ float g_q   [NN * 64];
__device__ int   g_cnt [NN];
__device__ int   g_roff[NN + 1];
__device__ int   g_cur [NN];
__device__ int   g_bsum[512];
__device__ int   g_esrc[EE];

// ---- tf32 helpers ----------------------------------------------------------
__device__ __forceinline__ unsigned to_tf32(float x)
{
    unsigned r; asm("cvt.rna.tf32.f32 %0, %1;" : "=r"(r) : "f"(x)); return r;
}
__device__ __forceinline__ void mma_tf32(float4& d, const unsigned* a, const unsigned* b)
{
    asm volatile(
        "mma.sync.aligned.m16n8k8.row.col.f32.tf32.tf32.f32 "
        "{%0,%1,%2,%3}, {%4,%5,%6,%7}, {%8,%9}, {%0,%1,%2,%3};"
        : "+f"(d.x), "+f"(d.y), "+f"(d.z), "+f"(d.w)
        : "r"(a[0]), "r"(a[1]), "r"(a[2]), "r"(a[3]), "r"(b[0]), "r"(b[1]));
}

// ---------------------------------------------------------------------------
// k = h@Wk, q = h@Wq, hw = h@W via 3xTF32 tensor-core MMA (fp32-class
// accuracy via hi/lo split). Runs on the SIDE stream, overlapped with the CSR
// chain. 192 threads = 6 warps = 3 matrices x 2 m-halves. (R10-12-proven.)
// ---------------------------------------------------------------------------
__global__ __launch_bounds__(192) void gemm_mma_kernel(
    const float* __restrict__ h,
    const float* __restrict__ Wk,
    const float* __restrict__ Wq,
    const float* __restrict__ Ww,
    int N)
{
    __shared__ float sA[32 * 72];        // sA[node][kdim]
    __shared__ float sW[3 * 64 * 72];    // sW[sel][kdim][col]

    const int tid = threadIdx.x;

    for (int idx = tid; idx < 64 * 64; idx += 192) {
        const int i = idx >> 6, c = idx & 63;
        sW[0 * 64 * 72 + i * 72 + c] = Wk[idx];
        sW[1 * 64 * 72 + i * 72 + c] = Wq[idx];
        sW[2 * 64 * 72 + i * 72 + c] = Ww[idx];
    }
    const int base = blockIdx.x * 32;
    for (int idx = tid; idx < 32 * 64; idx += 192) {
        const int n = idx >> 6, c = idx & 63;
        const int gn = base + n;
        sA[n * 72 + c] = (gn < N) ? h[(size_t)gn * 64 + c] : 0.f;
    }
    __syncthreads();

    const int wid  = tid >> 5;
    const int lane = tid & 31;
    const int sel  = wid >> 1;          // 0:Wk 1:Wq 2:Ww
    const int mh   = wid & 1;           // m-half (16 nodes)
    const int g    = lane >> 2;         // 0..7
    const int t4   = lane & 3;          // 0..3

    float4 acc[8];
#pragma unroll
    for (int nt = 0; nt < 8; nt++) acc[nt] = make_float4(0.f, 0.f, 0.f, 0.f);

    const float* wm = sW + sel * 64 * 72;

#pragma unroll
    for (int ks = 0; ks < 8; ks++) {
        const int r0 = (mh * 16 + g) * 72 + ks * 8 + t4;
        const int r1 = (mh * 16 + g + 8) * 72 + ks * 8 + t4;
        const float a0f = sA[r0],     a1f = sA[r1];
        const float a2f = sA[r0 + 4], a3f = sA[r1 + 4];

        unsigned ahi[4], alo[4];
        ahi[0] = to_tf32(a0f); alo[0] = to_tf32(a0f - __uint_as_float(ahi[0]));
        ahi[1] = to_tf32(a1f); alo[1] = to_tf32(a1f - __uint_as_float(ahi[1]));
        ahi[2] = to_tf32(a2f); alo[2] = to_tf32(a2f - __uint_as_float(ahi[2]));
        ahi[3] = to_tf32(a3f); alo[3] = to_tf32(a3f - __uint_as_float(ahi[3]));

#pragma unroll
        for (int nt = 0; nt < 8; nt++) {
            const float b0f = wm[(ks * 8 + t4) * 72 + nt * 8 + g];
            const float b1f = wm[(ks * 8 + t4 + 4) * 72 + nt * 8 + g];
            unsigned bhi[2], blo[2];
            bhi[0] = to_tf32(b0f); blo[0] = to_tf32(b0f - __uint_as_float(bhi[0]));
            bhi[1] = to_tf32(b1f); blo[1] = to_tf32(b1f - __uint_as_float(bhi[1]));

            mma_tf32(acc[nt], ahi, bhi);
            mma_tf32(acc[nt], ahi, blo);
            mma_tf32(acc[nt], alo, bhi);
        }
    }

    const int gn0 = base + mh * 16 + g;
    const int gn1 = gn0 + 8;
#pragma unroll
    for (int nt = 0; nt < 8; nt++) {
        const int col = nt * 8 + t4 * 2;
        if (sel == 0) {
            if (gn0 < N) *(float2*)&g_kw[(size_t)gn0 * 128 + col] = make_float2(acc[nt].x, acc[nt].y);
            if (gn1 < N) *(float2*)&g_kw[(size_t)gn1 * 128 + col] = make_float2(acc[nt].z, acc[nt].w);
        } else if (sel == 1) {
            if (gn0 < N) *(float2*)&g_q[(size_t)gn0 * 64 + col] = make_float2(acc[nt].x, acc[nt].y);
            if (gn1 < N) *(float2*)&g_q[(size_t)gn1 * 64 + col] = make_float2(acc[nt].z, acc[nt].w);
        } else {
            if (gn0 < N) *(float2*)&g_kw[(size_t)gn0 * 128 + 64 + col] = make_float2(acc[nt].x, acc[nt].y);
            if (gn1 < N) *(float2*)&g_kw[(size_t)gn1 * 128 + 64 + col] = make_float2(acc[nt].z, acc[nt].w);
        }
    }
}

// ---------------------------------------------------------------------------
// Histogram of dst (int4 loads)
// ---------------------------------------------------------------------------
__global__ void hist_kernel(const int* __restrict__ dst, int E)
{
    const int i4 = (blockIdx.x * blockDim.x + threadIdx.x) * 4;
    if (i4 + 3 < E) {
        const int4 d = *(const int4*)(dst + i4);
        atomicAdd(&g_cnt[d.x], 1);
        atomicAdd(&g_cnt[d.y], 1);
        atomicAdd(&g_cnt[d.z], 1);
        atomicAdd(&g_cnt[d.w], 1);
    } else {
        for (int j = i4; j < E; j++) atomicAdd(&g_cnt[dst[j]], 1);
    }
}

// ---------------------------------------------------------------------------
// Scan stage 1: per-block exclusive scan + block totals (no spinning).
// ---------------------------------------------------------------------------
__global__ __launch_bounds__(256) void scan1_kernel(int N)
{
    __shared__ int wsum[8];
    const int t = threadIdx.x, lane = t & 31, wd = t >> 5;
    const int i = blockIdx.x * 256 + t;
    const int v = (i < N) ? g_cnt[i] : 0;
    int x = v;
#pragma unroll
    for (int off = 1; off < 32; off <<= 1) {
        int y = __shfl_up_sync(0xffffffffu, x, off);
        if (lane >= off) x += y;
    }
    if (lane == 31) wsum[wd] = x;
    __syncthreads();
    if (t < 8) {
        int w = wsum[t];
        int xs = w;
#pragma unroll
        for (int off = 1; off < 8; off <<= 1) {
            int y = __shfl_up_sync(0x000000ffu, xs, off);
            if (t >= off) xs += y;
        }
        wsum[t] = xs - w;                       // exclusive warp offset
        if (t == 7) g_bsum[blockIdx.x] = xs;    // block total
    }
    __syncthreads();
    if (i < N) g_roff[i] = x - v + wsum[wd];
}

// ---------------------------------------------------------------------------
// Scan stage 2+3 merged: each block recomputes its block-prefix from g_bsum
// (block reduce over < nb ints — cheap, redundant, spin-free), then applies.
// ---------------------------------------------------------------------------
__global__ __launch_bounds__(256) void scan23_kernel(int N, int E, int nb)
{
    __shared__ int wred[8];
    const int t = threadIdx.x, lane = t & 31, wd = t >> 5;
    const int bid = blockIdx.x;

    int acc = 0;
    for (int j = t; j < bid; j += 256) acc += g_bsum[j];
#pragma unroll
    for (int off = 16; off > 0; off >>= 1)
        acc += __shfl_xor_sync(0xffffffffu, acc, off);
    if (lane == 0) wred[wd] = acc;
    __syncthreads();
    if (t == 0) {
        int s = 0;
#pragma unroll
        for (int j = 0; j < 8; j++) s += wred[j];
        wred[0] = s;
    }
    __syncthreads();
    const int boff = wred[0];

    const int i = bid * 256 + t;
    if (i < N) {
        const int r = g_roff[i] + boff;
        g_roff[i] = r;
        g_cur[i]  = r;
    }
    if (bid == 0 && t == 0) g_roff[N] = E;
}

// ---------------------------------------------------------------------------
// Scatter src ids into CSR order (int4 loads)
// ---------------------------------------------------------------------------
__global__ void scatter_kernel(const int* __restrict__ src,
                               const int* __restrict__ dst, int E)
{
    const int i4 = (blockIdx.x * blockDim.x + threadIdx.x) * 4;
    if (i4 + 3 < E) {
        const int4 d = *(const int4*)(dst + i4);
        const int4 s = *(const int4*)(src + i4);
        g_esrc[atomicAdd(&g_cur[d.x], 1)] = s.x;
        g_esrc[atomicAdd(&g_cur[d.y], 1)] = s.y;
        g_esrc[atomicAdd(&g_cur[d.z], 1)] = s.z;
        g_esrc[atomicAdd(&g_cur[d.w], 1)] = s.w;
    } else {
        for (int j = i4; j < E; j++)
            g_esrc[atomicAdd(&g_cur[dst[j]], 1)] = src[j];
    }
}

// ---------------------------------------------------------------------------
// Fused edge-softmax + aggregation (R12-proven 2-deep pipeline, plain LDG/STG).
// 64-THREAD BLOCKS: 2 warps per block so a straggler node holds only a 2-warp
// slot instead of 8 -> better SM work conservation under Poisson(16) degrees.
// ---------------------------------------------------------------------------
__global__ __launch_bounds__(64) void gather_kernel(
    const float* __restrict__ b,
    float* __restrict__ out,
    int N)
{
    const int n    = (blockIdx.x * 64 + threadIdx.x) >> 5;
    const int lane = threadIdx.x & 31;
    if (n >= N) return;
    const int hh = lane >> 3;   // own head

    const float2 q2 = ((const float2*)(g_q + (size_t)n * 64))[lane];
    const int p0 = g_roff[n];
    const int p1 = g_roff[n + 1];

    float2 a0 = make_float2(0.f, 0.f), a1 = a0, a2 = a0, a3 = a0;
    float z0 = 0.f;

#define GK_LOAD(kk, ww, sid)                                              \
    do {                                                                  \
        const float2* _kp = (const float2*)(g_kw + (size_t)(sid) * 128);  \
        kk = _kp[lane];                                                   \
        ww = _kp[lane + 32];                                              \
    } while (0)

#define GK_CONSUME(kk, ww)                                                \
    do {                                                                  \
        float prod = kk.x * q2.x + kk.y * q2.y;                           \
        prod += __shfl_xor_sync(0xffffffffu, prod, 4);                    \
        prod += __shfl_xor_sync(0xffffffffu, prod, 2);                    \
        prod += __shfl_xor_sync(0xffffffffu, prod, 1);                    \
        const float ew = __expf(prod);                                    \
        const float eA = __shfl_xor_sync(0xffffffffu, ew, 8);             \
        const float eB = __shfl_xor_sync(0xffffffffu, ew, 16);            \
        const float eC = __shfl_xor_sync(0xffffffffu, ew, 24);            \
        z0 += ew;                                                         \
        a0.x += ew * ww.x; a0.y += ew * ww.y;                             \
        a1.x += eA * ww.x; a1.y += eA * ww.y;                             \
        a2.x += eB * ww.x; a2.y += eB * ww.y;                             \
        a3.x += eC * ww.x; a3.y += eC * ww.y;                             \
    } while (0)

    if (p0 < p1) {
        float2 ka, wa, kb, wb;
        GK_LOAD(ka, wa, g_esrc[p0]);
        if (p0 + 1 < p1) GK_LOAD(kb, wb, g_esrc[p0 + 1]);

        int p = p0;
        for (; p + 1 < p1; p += 2) {
            float2 kn0 = ka, wn0 = wa, kn1 = kb, wn1 = wb;
            if (p + 2 < p1) GK_LOAD(kn0, wn0, g_esrc[p + 2]);
            if (p + 3 < p1) GK_LOAD(kn1, wn1, g_esrc[p + 3]);

            GK_CONSUME(ka, wa);
            GK_CONSUME(kb, wb);

            ka = kn0; wa = wn0; kb = kn1; wb = wn1;
        }
        if (p < p1) GK_CONSUME(ka, wa);
    }
#undef GK_LOAD
#undef GK_CONSUME

    // other heads' z from own-head lanes
    const float z1 = __shfl_xor_sync(0xffffffffu, z0, 8);
    const float z2 = __shfl_xor_sync(0xffffffffu, z0, 16);
    const float z3 = __shfl_xor_sync(0xffffffffu, z0, 24);

    const float i0 = (z0 > 0.f) ? 1.f / z0 : 0.f;
    const float i1 = (z1 > 0.f) ? 1.f / z1 : 0.f;
    const float i2 = (z2 > 0.f) ? 1.f / z2 : 0.f;
    const float i3 = (z3 > 0.f) ? 1.f / z3 : 0.f;

    const float2 bb = ((const float2*)b)[lane];   // features 2l, 2l+1
    float* op = out + (size_t)n * 256 + 2 * lane;

    *(float2*)(op + (size_t)(hh     ) * 64) = make_float2(a0.x * i0 + bb.x, a0.y * i0 + bb.y);
    *(float2*)(op + (size_t)(hh ^ 1) * 64) = make_float2(a1.x * i1 + bb.x, a1.y * i1 + bb.y);
    *(float2*)(op + (size_t)(hh ^ 2) * 64) = make_float2(a2.x * i2 + bb.x, a2.y * i2 + bb.y);
    *(float2*)(op + (size_t)(hh ^ 3) * 64) = make_float2(a3.x * i3 + bb.x, a3.y * i3 + bb.y);
}

// ---------------------------------------------------------------------------
extern "C" void kernel_launch(void* const* d_in, const int* in_sizes, int n_in,
                              void* d_out, int out_size)
{
    const float* h   = (const float*)d_in[0];
    const int*   src = (const int*)  d_in[1];
    const int*   dst = (const int*)  d_in[2];
    const float* Wk  = (const float*)d_in[3];
    const float* Wq  = (const float*)d_in[4];
    const float* Ww  = (const float*)d_in[5];
    const float* b   = (const float*)d_in[6];
    float*       out = (float*)d_out;

    const int N  = in_sizes[0] / 64;
    const int E  = in_sizes[1];
    const int nb = (N + 255) / 256;

    static void* cnt_ptr = nullptr;
    static cudaStream_t sideStream = nullptr;
    static cudaEvent_t  evFork = nullptr, evJoin = nullptr;
    if (cnt_ptr == nullptr) {
        cudaGetSymbolAddress(&cnt_ptr, g_cnt);
        cudaStreamCreateWithFlags(&sideStream, cudaStreamNonBlocking);
        cudaEventCreateWithFlags(&evFork, cudaEventDisableTiming);
        cudaEventCreateWithFlags(&evJoin, cudaEventDisableTiming);
    }

    // Fork: pure gemm (h,W only) overlaps the whole CSR chain (src,dst only).
    cudaEventRecord(evFork, 0);
    cudaStreamWaitEvent(sideStream, evFork, 0);
    gemm_mma_kernel<<<(N + 31) / 32, 192, 0, sideStream>>>(h, Wk, Wq, Ww, N);
    cudaEventRecord(evJoin, sideStream);

    cudaMemsetAsync(cnt_ptr, 0, (size_t)N * sizeof(int));
    hist_kernel<<<(E / 4 + 255) / 256, 256>>>(dst, E);
    scan1_kernel<<<nb, 256>>>(N);
    scan23_kernel<<<nb, 256>>>(N, E, nb);
    scatter_kernel<<<(E / 4 + 255) / 256, 256>>>(src, dst, E);

    cudaStreamWaitEvent(0, evJoin, 0);
    gather_kernel<<<(N + 1) / 2, 64>>>(b, out, N);
}

// round 16
// speedup vs baseline: 1.2458x; 1.1574x over previous
#include <cuda_runtime.h>

#define NN 100000
#define EE 1600000

// Scratch (allocation-free rule: __device__ globals)
__device__ float g_kw  [NN * 128];  // interleaved: [n][0:64]=k row, [n][64:128]=hw row
__device__ float g_q   [NN * 64];
__device__ int   g_cnt [NN];
__device__ int   g_roff[NN + 1];
__device__ int   g_cur [NN];
__device__ int   g_bsum[512];
__device__ int   g_esrc[EE];

// ---- tf32 helpers ----------------------------------------------------------
__device__ __forceinline__ unsigned to_tf32(float x)
{
    unsigned r; asm("cvt.rna.tf32.f32 %0, %1;" : "=r"(r) : "f"(x)); return r;
}
__device__ __forceinline__ void mma_tf32(float4& d, const unsigned* a, const unsigned* b)
{
    asm volatile(
        "mma.sync.aligned.m16n8k8.row.col.f32.tf32.tf32.f32 "
        "{%0,%1,%2,%3}, {%4,%5,%6,%7}, {%8,%9}, {%0,%1,%2,%3};"
        : "+f"(d.x), "+f"(d.y), "+f"(d.z), "+f"(d.w)
        : "r"(a[0]), "r"(a[1]), "r"(a[2]), "r"(a[3]), "r"(b[0]), "r"(b[1]));
}

// ---------------------------------------------------------------------------
// k = h@Wk, q = h@Wq, hw = h@W via 3xTF32 tensor-core MMA (fp32-class
// accuracy via hi/lo split). 128 nodes per block in four 32-node sub-tiles;
// weights staged ONCE per block (48 KB) -> 4x less weight traffic than the
// 32-node version. 192 threads = 6 warps = 3 matrices x 2 m-halves.
// ---------------------------------------------------------------------------
__global__ __launch_bounds__(192) void gemm_mma_kernel(
    const float* __restrict__ h,
    const float* __restrict__ Wk,
    const float* __restrict__ Wq,
    const float* __restrict__ Ww,
    int N)
{
    __shared__ float sA[32 * 72];        // sA[node][kdim] (per sub-tile)
    __shared__ float sW[3 * 64 * 72];    // sW[sel][kdim][col]

    const int tid = threadIdx.x;

    for (int idx = tid; idx < 64 * 64; idx += 192) {
        const int i = idx >> 6, c = idx & 63;
        sW[0 * 64 * 72 + i * 72 + c] = Wk[idx];
        sW[1 * 64 * 72 + i * 72 + c] = Wq[idx];
        sW[2 * 64 * 72 + i * 72 + c] = Ww[idx];
    }

    const int wid  = tid >> 5;
    const int lane = tid & 31;
    const int sel  = wid >> 1;          // 0:Wk 1:Wq 2:Ww
    const int mh   = wid & 1;           // m-half (16 nodes)
    const int g    = lane >> 2;         // 0..7
    const int t4   = lane & 3;          // 0..3
    const float* wm = sW + sel * 64 * 72;

    for (int st = 0; st < 4; st++) {
        const int base = blockIdx.x * 128 + st * 32;
        __syncthreads();   // protects sA from previous sub-tile's readers
        for (int idx = tid; idx < 32 * 64; idx += 192) {
            const int n = idx >> 6, c = idx & 63;
            const int gn = base + n;
            sA[n * 72 + c] = (gn < N) ? h[(size_t)gn * 64 + c] : 0.f;
        }
        __syncthreads();

        float4 acc[8];
#pragma unroll
        for (int nt = 0; nt < 8; nt++) acc[nt] = make_float4(0.f, 0.f, 0.f, 0.f);

#pragma unroll
        for (int ks = 0; ks < 8; ks++) {
            const int r0 = (mh * 16 + g) * 72 + ks * 8 + t4;
            const int r1 = (mh * 16 + g + 8) * 72 + ks * 8 + t4;
            const float a0f = sA[r0],     a1f = sA[r1];
            const float a2f = sA[r0 + 4], a3f = sA[r1 + 4];

            unsigned ahi[4], alo[4];
            ahi[0] = to_tf32(a0f); alo[0] = to_tf32(a0f - __uint_as_float(ahi[0]));
            ahi[1] = to_tf32(a1f); alo[1] = to_tf32(a1f - __uint_as_float(ahi[1]));
            ahi[2] = to_tf32(a2f); alo[2] = to_tf32(a2f - __uint_as_float(ahi[2]));
            ahi[3] = to_tf32(a3f); alo[3] = to_tf32(a3f - __uint_as_float(ahi[3]));

#pragma unroll
            for (int nt = 0; nt < 8; nt++) {
                const float b0f = wm[(ks * 8 + t4) * 72 + nt * 8 + g];
                const float b1f = wm[(ks * 8 + t4 + 4) * 72 + nt * 8 + g];
                unsigned bhi[2], blo[2];
                bhi[0] = to_tf32(b0f); blo[0] = to_tf32(b0f - __uint_as_float(bhi[0]));
                bhi[1] = to_tf32(b1f); blo[1] = to_tf32(b1f - __uint_as_float(bhi[1]));

                mma_tf32(acc[nt], ahi, bhi);
                mma_tf32(acc[nt], ahi, blo);
                mma_tf32(acc[nt], alo, bhi);
            }
        }

        const int gn0 = base + mh * 16 + g;
        const int gn1 = gn0 + 8;
#pragma unroll
        for (int nt = 0; nt < 8; nt++) {
            const int col = nt * 8 + t4 * 2;
            if (sel == 0) {
                if (gn0 < N) *(float2*)&g_kw[(size_t)gn0 * 128 + col] = make_float2(acc[nt].x, acc[nt].y);
                if (gn1 < N) *(float2*)&g_kw[(size_t)gn1 * 128 + col] = make_float2(acc[nt].z, acc[nt].w);
            } else if (sel == 1) {
                if (gn0 < N) *(float2*)&g_q[(size_t)gn0 * 64 + col] = make_float2(acc[nt].x, acc[nt].y);
                if (gn1 < N) *(float2*)&g_q[(size_t)gn1 * 64 + col] = make_float2(acc[nt].z, acc[nt].w);
            } else {
                if (gn0 < N) *(float2*)&g_kw[(size_t)gn0 * 128 + 64 + col] = make_float2(acc[nt].x, acc[nt].y);
                if (gn1 < N) *(float2*)&g_kw[(size_t)gn1 * 128 + 64 + col] = make_float2(acc[nt].z, acc[nt].w);
            }
        }
    }
}

// ---------------------------------------------------------------------------
// Histogram of dst (int4 loads)
// ---------------------------------------------------------------------------
__global__ void hist_kernel(const int* __restrict__ dst, int E)
{
    const int i4 = (blockIdx.x * blockDim.x + threadIdx.x) * 4;
    if (i4 + 3 < E) {
        const int4 d = *(const int4*)(dst + i4);
        atomicAdd(&g_cnt[d.x], 1);
        atomicAdd(&g_cnt[d.y], 1);
        atomicAdd(&g_cnt[d.z], 1);
        atomicAdd(&g_cnt[d.w], 1);
    } else {
        for (int j = i4; j < E; j++) atomicAdd(&g_cnt[dst[j]], 1);
    }
}

// ---------------------------------------------------------------------------
// Scan stage 1: per-block exclusive scan + block totals (no spinning).
// ---------------------------------------------------------------------------
__global__ __launch_bounds__(256) void scan1_kernel(int N)
{
    __shared__ int wsum[8];
    const int t = threadIdx.x, lane = t & 31, wd = t >> 5;
    const int i = blockIdx.x * 256 + t;
    const int v = (i < N) ? g_cnt[i] : 0;
    int x = v;
#pragma unroll
    for (int off = 1; off < 32; off <<= 1) {
        int y = __shfl_up_sync(0xffffffffu, x, off);
        if (lane >= off) x += y;
    }
    if (lane == 31) wsum[wd] = x;
    __syncthreads();
    if (t < 8) {
        int w = wsum[t];
        int xs = w;
#pragma unroll
        for (int off = 1; off < 8; off <<= 1) {
            int y = __shfl_up_sync(0x000000ffu, xs, off);
            if (t >= off) xs += y;
        }
        wsum[t] = xs - w;                       // exclusive warp offset
        if (t == 7) g_bsum[blockIdx.x] = xs;    // block total
    }
    __syncthreads();
    if (i < N) g_roff[i] = x - v + wsum[wd];
}

// ---------------------------------------------------------------------------
// Scan stage 2+3 merged: each block recomputes its block-prefix from g_bsum
// (block reduce over < nb ints — cheap, redundant, spin-free), then applies.
// ---------------------------------------------------------------------------
__global__ __launch_bounds__(256) void scan23_kernel(int N, int E, int nb)
{
    __shared__ int wred[8];
    const int t = threadIdx.x, lane = t & 31, wd = t >> 5;
    const int bid = blockIdx.x;

    int acc = 0;
    for (int j = t; j < bid; j += 256) acc += g_bsum[j];
#pragma unroll
    for (int off = 16; off > 0; off >>= 1)
        acc += __shfl_xor_sync(0xffffffffu, acc, off);
    if (lane == 0) wred[wd] = acc;
    __syncthreads();
    if (t == 0) {
        int s = 0;
#pragma unroll
        for (int j = 0; j < 8; j++) s += wred[j];
        wred[0] = s;
    }
    __syncthreads();
    const int boff = wred[0];

    const int i = bid * 256 + t;
    if (i < N) {
        const int r = g_roff[i] + boff;
        g_roff[i] = r;
        g_cur[i]  = r;
    }
    if (bid == 0 && t == 0) g_roff[N] = E;
}

// ---------------------------------------------------------------------------
// Scatter src ids into CSR order (int4 loads)
// ---------------------------------------------------------------------------
__global__ void scatter_kernel(const int* __restrict__ src,
                               const int* __restrict__ dst, int E)
{
    const int i4 = (blockIdx.x * blockDim.x + threadIdx.x) * 4;
    if (i4 + 3 < E) {
        const int4 d = *(const int4*)(dst + i4);
        const int4 s = *(const int4*)(src + i4);
        g_esrc[atomicAdd(&g_cur[d.x], 1)] = s.x;
        g_esrc[atomicAdd(&g_cur[d.y], 1)] = s.y;
        g_esrc[atomicAdd(&g_cur[d.z], 1)] = s.z;
        g_esrc[atomicAdd(&g_cur[d.w], 1)] = s.w;
    } else {
        for (int j = i4; j < E; j++)
            g_esrc[atomicAdd(&g_cur[dst[j]], 1)] = src[j];
    }
}

// ---------------------------------------------------------------------------
// Fused edge-softmax + aggregation (R12/R15-proven: 2-deep pipeline, 64-thread
// blocks for straggler containment, plain LDG/STG).
// ---------------------------------------------------------------------------
__global__ __launch_bounds__(64) void gather_kernel(
    const float* __restrict__ b,
    float* __restrict__ out,
    int N)
{
    const int n    = (blockIdx.x * 64 + threadIdx.x) >> 5;
    const int lane = threadIdx.x & 31;
    if (n >= N) return;
    const int hh = lane >> 3;   // own head

    const float2 q2 = ((const float2*)(g_q + (size_t)n * 64))[lane];
    const int p0 = g_roff[n];
    const int p1 = g_roff[n + 1];

    float2 a0 = make_float2(0.f, 0.f), a1 = a0, a2 = a0, a3 = a0;
    float z0 = 0.f;

#define GK_LOAD(kk, ww, sid)                                              \
    do {                                                                  \
        const float2* _kp = (const float2*)(g_kw + (size_t)(sid) * 128);  \
        kk = _kp[lane];                                                   \
        ww = _kp[lane + 32];                                              \
    } while (0)

#define GK_CONSUME(kk, ww)                                                \
    do {                                                                  \
        float prod = kk.x * q2.x + kk.y * q2.y;                           \
        prod += __shfl_xor_sync(0xffffffffu, prod, 4);                    \
        prod += __shfl_xor_sync(0xffffffffu, prod, 2);                    \
        prod += __shfl_xor_sync(0xffffffffu, prod, 1);                    \
        const float ew = __expf(prod);                                    \
        const float eA = __shfl_xor_sync(0xffffffffu, ew, 8);             \
        const float eB = __shfl_xor_sync(0xffffffffu, ew, 16);            \
        const float eC = __shfl_xor_sync(0xffffffffu, ew, 24);            \
        z0 += ew;                                                         \
        a0.x += ew * ww.x; a0.y += ew * ww.y;                             \
        a1.x += eA * ww.x; a1.y += eA * ww.y;                             \
        a2.x += eB * ww.x; a2.y += eB * ww.y;                             \
        a3.x += eC * ww.x; a3.y += eC * ww.y;                             \
    } while (0)

    if (p0 < p1) {
        float2 ka, wa, kb, wb;
        GK_LOAD(ka, wa, g_esrc[p0]);
        if (p0 + 1 < p1) GK_LOAD(kb, wb, g_esrc[p0 + 1]);

        int p = p0;
        for (; p + 1 < p1; p += 2) {
            float2 kn0 = ka, wn0 = wa, kn1 = kb, wn1 = wb;
            if (p + 2 < p1) GK_LOAD(kn0, wn0, g_esrc[p + 2]);
            if (p + 3 < p1) GK_LOAD(kn1, wn1, g_esrc[p + 3]);

            GK_CONSUME(ka, wa);
            GK_CONSUME(kb, wb);

            ka = kn0; wa = wn0; kb = kn1; wb = wn1;
        }
        if (p < p1) GK_CONSUME(ka, wa);
    }
#undef GK_LOAD
#undef GK_CONSUME

    // other heads' z from own-head lanes
    const float z1 = __shfl_xor_sync(0xffffffffu, z0, 8);
    const float z2 = __shfl_xor_sync(0xffffffffu, z0, 16);
    const float z3 = __shfl_xor_sync(0xffffffffu, z0, 24);

    const float i0 = (z0 > 0.f) ? 1.f / z0 : 0.f;
    const float i1 = (z1 > 0.f) ? 1.f / z1 : 0.f;
    const float i2 = (z2 > 0.f) ? 1.f / z2 : 0.f;
    const float i3 = (z3 > 0.f) ? 1.f / z3 : 0.f;

    const float2 bb = ((const float2*)b)[lane];   // features 2l, 2l+1
    float* op = out + (size_t)n * 256 + 2 * lane;

    *(float2*)(op + (size_t)(hh     ) * 64) = make_float2(a0.x * i0 + bb.x, a0.y * i0 + bb.y);
    *(float2*)(op + (size_t)(hh ^ 1) * 64) = make_float2(a1.x * i1 + bb.x, a1.y * i1 + bb.y);
    *(float2*)(op + (size_t)(hh ^ 2) * 64) = make_float2(a2.x * i2 + bb.x, a2.y * i2 + bb.y);
    *(float2*)(op + (size_t)(hh ^ 3) * 64) = make_float2(a3.x * i3 + bb.x, a3.y * i3 + bb.y);
}

// ---------------------------------------------------------------------------
extern "C" void kernel_launch(void* const* d_in, const int* in_sizes, int n_in,
                              void* d_out, int out_size)
{
    const float* h   = (const float*)d_in[0];
    const int*   src = (const int*)  d_in[1];
    const int*   dst = (const int*)  d_in[2];
    const float* Wk  = (const float*)d_in[3];
    const float* Wq  = (const float*)d_in[4];
    const float* Ww  = (const float*)d_in[5];
    const float* b   = (const float*)d_in[6];
    float*       out = (float*)d_out;

    const int N  = in_sizes[0] / 64;
    const int E  = in_sizes[1];
    const int nb = (N + 255) / 256;

    static void* cnt_ptr = nullptr;
    static cudaStream_t sideStream = nullptr;
    static cudaEvent_t  evFork = nullptr, evJoin = nullptr;
    if (cnt_ptr == nullptr) {
        cudaGetSymbolAddress(&cnt_ptr, g_cnt);
        cudaStreamCreateWithFlags(&sideStream, cudaStreamNonBlocking);
        cudaEventCreateWithFlags(&evFork, cudaEventDisableTiming);
        cudaEventCreateWithFlags(&evJoin, cudaEventDisableTiming);
    }

    // Fork: pure gemm (h,W only) overlaps the whole CSR chain (src,dst only).
    cudaEventRecord(evFork, 0);
    cudaStreamWaitEvent(sideStream, evFork, 0);
    gemm_mma_kernel<<<(N + 127) / 128, 192, 0, sideStream>>>(h, Wk, Wq, Ww, N);
    cudaEventRecord(evJoin, sideStream);

    cudaMemsetAsync(cnt_ptr, 0, (size_t)N * sizeof(int));
    hist_kernel<<<(E / 4 + 255) / 256, 256>>>(dst, E);
    scan1_kernel<<<nb, 256>>>(N);
    scan23_kernel<<<nb, 256>>>(N, E, nb);
    scatter_kernel<<<(E / 4 + 255) / 256, 256>>>(src, dst, E);

    cudaStreamWaitEvent(0, evJoin, 0);
    gather_kernel<<<(N + 1) / 2, 64>>>(b, out, N);
}

// round 17
// speedup vs baseline: 1.2553x; 1.0077x over previous
#include <cuda_runtime.h>
#include <cuda_fp16.h>

#define NN 100000
#define EE 1600000

// Scratch (allocation-free rule: __device__ globals)
// g_kw row (96 floats = 384 B): [0:64) k fp32, [64:96) = 64 fp16 hw values
__device__ float g_kw  [NN * 96];
__device__ float g_q   [NN * 64];
__device__ int   g_cnt [NN];
__device__ int   g_roff[NN + 1];
__device__ int   g_cur [NN];
__device__ int   g_bsum[512];
__device__ int   g_esrc[EE];

// ---- tf32 helpers ----------------------------------------------------------
__device__ __forceinline__ unsigned to_tf32(float x)
{
    unsigned r; asm("cvt.rna.tf32.f32 %0, %1;" : "=r"(r) : "f"(x)); return r;
}
__device__ __forceinline__ void mma_tf32(float4& d, const unsigned* a, const unsigned* b)
{
    asm volatile(
        "mma.sync.aligned.m16n8k8.row.col.f32.tf32.tf32.f32 "
        "{%0,%1,%2,%3}, {%4,%5,%6,%7}, {%8,%9}, {%0,%1,%2,%3};"
        : "+f"(d.x), "+f"(d.y), "+f"(d.z), "+f"(d.w)
        : "r"(a[0]), "r"(a[1]), "r"(a[2]), "r"(a[3]), "r"(b[0]), "r"(b[1]));
}

// ---------------------------------------------------------------------------
// k = h@Wk, q = h@Wq, hw = h@W via 3xTF32 tensor-core MMA (fp32-class
// accuracy via hi/lo split). 128 nodes per block in four 32-node sub-tiles;
// weights staged ONCE per block. hw is stored as fp16 (value path — output is
// a convex combination of hw rows, so per-element rel err ~2.4e-4 << 1e-3).
// ---------------------------------------------------------------------------
__global__ __launch_bounds__(192) void gemm_mma_kernel(
    const float* __restrict__ h,
    const float* __restrict__ Wk,
    const float* __restrict__ Wq,
    const float* __restrict__ Ww,
    int N)
{
    __shared__ float sA[32 * 72];        // sA[node][kdim] (per sub-tile)
    __shared__ float sW[3 * 64 * 72];    // sW[sel][kdim][col]

    const int tid = threadIdx.x;

    for (int idx = tid; idx < 64 * 64; idx += 192) {
        const int i = idx >> 6, c = idx & 63;
        sW[0 * 64 * 72 + i * 72 + c] = Wk[idx];
        sW[1 * 64 * 72 + i * 72 + c] = Wq[idx];
        sW[2 * 64 * 72 + i * 72 + c] = Ww[idx];
    }

    const int wid  = tid >> 5;
    const int lane = tid & 31;
    const int sel  = wid >> 1;          // 0:Wk 1:Wq 2:Ww
    const int mh   = wid & 1;           // m-half (16 nodes)
    const int g    = lane >> 2;         // 0..7
    const int t4   = lane & 3;          // 0..3
    const float* wm = sW + sel * 64 * 72;

    for (int st = 0; st < 4; st++) {
        const int base = blockIdx.x * 128 + st * 32;
        __syncthreads();   // protects sA from previous sub-tile's readers
        for (int idx = tid; idx < 32 * 64; idx += 192) {
            const int n = idx >> 6, c = idx & 63;
            const int gn = base + n;
            sA[n * 72 + c] = (gn < N) ? h[(size_t)gn * 64 + c] : 0.f;
        }
        __syncthreads();

        float4 acc[8];
#pragma unroll
        for (int nt = 0; nt < 8; nt++) acc[nt] = make_float4(0.f, 0.f, 0.f, 0.f);

#pragma unroll
        for (int ks = 0; ks < 8; ks++) {
            const int r0 = (mh * 16 + g) * 72 + ks * 8 + t4;
            const int r1 = (mh * 16 + g + 8) * 72 + ks * 8 + t4;
            const float a0f = sA[r0],     a1f = sA[r1];
            const float a2f = sA[r0 + 4], a3f = sA[r1 + 4];

            unsigned ahi[4], alo[4];
            ahi[0] = to_tf32(a0f); alo[0] = to_tf32(a0f - __uint_as_float(ahi[0]));
            ahi[1] = to_tf32(a1f); alo[1] = to_tf32(a1f - __uint_as_float(ahi[1]));
            ahi[2] = to_tf32(a2f); alo[2] = to_tf32(a2f - __uint_as_float(ahi[2]));
            ahi[3] = to_tf32(a3f); alo[3] = to_tf32(a3f - __uint_as_float(ahi[3]));

#pragma unroll
            for (int nt = 0; nt < 8; nt++) {
                const float b0f = wm[(ks * 8 + t4) * 72 + nt * 8 + g];
                const float b1f = wm[(ks * 8 + t4 + 4) * 72 + nt * 8 + g];
                unsigned bhi[2], blo[2];
                bhi[0] = to_tf32(b0f); blo[0] = to_tf32(b0f - __uint_as_float(bhi[0]));
                bhi[1] = to_tf32(b1f); blo[1] = to_tf32(b1f - __uint_as_float(bhi[1]));

                mma_tf32(acc[nt], ahi, bhi);
                mma_tf32(acc[nt], ahi, blo);
                mma_tf32(acc[nt], alo, bhi);
            }
        }

        const int gn0 = base + mh * 16 + g;
        const int gn1 = gn0 + 8;
#pragma unroll
        for (int nt = 0; nt < 8; nt++) {
            const int col = nt * 8 + t4 * 2;
            if (sel == 0) {
                if (gn0 < N) *(float2*)&g_kw[(size_t)gn0 * 96 + col] = make_float2(acc[nt].x, acc[nt].y);
                if (gn1 < N) *(float2*)&g_kw[(size_t)gn1 * 96 + col] = make_float2(acc[nt].z, acc[nt].w);
            } else if (sel == 1) {
                if (gn0 < N) *(float2*)&g_q[(size_t)gn0 * 64 + col] = make_float2(acc[nt].x, acc[nt].y);
                if (gn1 < N) *(float2*)&g_q[(size_t)gn1 * 64 + col] = make_float2(acc[nt].z, acc[nt].w);
            } else {
                if (gn0 < N)
                    *(__half2*)((__half*)(g_kw + (size_t)gn0 * 96 + 64) + col) =
                        __floats2half2_rn(acc[nt].x, acc[nt].y);
                if (gn1 < N)
                    *(__half2*)((__half*)(g_kw + (size_t)gn1 * 96 + 64) + col) =
                        __floats2half2_rn(acc[nt].z, acc[nt].w);
            }
        }
    }
}

// ---------------------------------------------------------------------------
// Histogram of dst (int4 loads)
// ---------------------------------------------------------------------------
__global__ void hist_kernel(const int* __restrict__ dst, int E)
{
    const int i4 = (blockIdx.x * blockDim.x + threadIdx.x) * 4;
    if (i4 + 3 < E) {
        const int4 d = *(const int4*)(dst + i4);
        atomicAdd(&g_cnt[d.x], 1);
        atomicAdd(&g_cnt[d.y], 1);
        atomicAdd(&g_cnt[d.z], 1);
        atomicAdd(&g_cnt[d.w], 1);
    } else {
        for (int j = i4; j < E; j++) atomicAdd(&g_cnt[dst[j]], 1);
    }
}

// ---------------------------------------------------------------------------
// Scan stage 1: per-block exclusive scan + block totals (no spinning).
// ---------------------------------------------------------------------------
__global__ __launch_bounds__(256) void scan1_kernel(int N)
{
    __shared__ int wsum[8];
    const int t = threadIdx.x, lane = t & 31, wd = t >> 5;
    const int i = blockIdx.x * 256 + t;
    const int v = (i < N) ? g_cnt[i] : 0;
    int x = v;
#pragma unroll
    for (int off = 1; off < 32; off <<= 1) {
        int y = __shfl_up_sync(0xffffffffu, x, off);
        if (lane >= off) x += y;
    }
    if (lane == 31) wsum[wd] = x;
    __syncthreads();
    if (t < 8) {
        int w = wsum[t];
        int xs = w;
#pragma unroll
        for (int off = 1; off < 8; off <<= 1) {
            int y = __shfl_up_sync(0x000000ffu, xs, off);
            if (t >= off) xs += y;
        }
        wsum[t] = xs - w;                       // exclusive warp offset
        if (t == 7) g_bsum[blockIdx.x] = xs;    // block total
    }
    __syncthreads();
    if (i < N) g_roff[i] = x - v + wsum[wd];
}

// ---------------------------------------------------------------------------
// Scan stage 2+3 merged: each block recomputes its block-prefix from g_bsum
// (block reduce over < nb ints — cheap, redundant, spin-free), then applies.
// ---------------------------------------------------------------------------
__global__ __launch_bounds__(256) void scan23_kernel(int N, int E, int nb)
{
    __shared__ int wred[8];
    const int t = threadIdx.x, lane = t & 31, wd = t >> 5;
    const int bid = blockIdx.x;

    int acc = 0;
    for (int j = t; j < bid; j += 256) acc += g_bsum[j];
#pragma unroll
    for (int off = 16; off > 0; off >>= 1)
        acc += __shfl_xor_sync(0xffffffffu, acc, off);
    if (lane == 0) wred[wd] = acc;
    __syncthreads();
    if (t == 0) {
        int s = 0;
#pragma unroll
        for (int j = 0; j < 8; j++) s += wred[j];
        wred[0] = s;
    }
    __syncthreads();
    const int boff = wred[0];

    const int i = bid * 256 + t;
    if (i < N) {
        const int r = g_roff[i] + boff;
        g_roff[i] = r;
        g_cur[i]  = r;
    }
    if (bid == 0 && t == 0) g_roff[N] = E;
}

// ---------------------------------------------------------------------------
// Scatter src ids into CSR order (int4 loads)
// ---------------------------------------------------------------------------
__global__ void scatter_kernel(const int* __restrict__ src,
                               const int* __restrict__ dst, int E)
{
    const int i4 = (blockIdx.x * blockDim.x + threadIdx.x) * 4;
    if (i4 + 3 < E) {
        const int4 d = *(const int4*)(dst + i4);
        const int4 s = *(const int4*)(src + i4);
        g_esrc[atomicAdd(&g_cur[d.x], 1)] = s.x;
        g_esrc[atomicAdd(&g_cur[d.y], 1)] = s.y;
        g_esrc[atomicAdd(&g_cur[d.z], 1)] = s.z;
        g_esrc[atomicAdd(&g_cur[d.w], 1)] = s.w;
    } else {
        for (int j = i4; j < E; j++)
            g_esrc[atomicAdd(&g_cur[dst[j]], 1)] = src[j];
    }
}

// ---------------------------------------------------------------------------
// Fused edge-softmax + aggregation (2-deep pipeline, 64-thread blocks).
// Edge row = 384 B: k fp32 (dot path, exact) + hw fp16 (value path).
// Per lane per edge: one LDG.64 (k) + one LDG.32 (hw half2) -> 12 B.
// ---------------------------------------------------------------------------
__global__ __launch_bounds__(64) void gather_kernel(
    const float* __restrict__ b,
    float* __restrict__ out,
    int N)
{
    const int n    = (blockIdx.x * 64 + threadIdx.x) >> 5;
    const int lane = threadIdx.x & 31;
    if (n >= N) return;
    const int hh = lane >> 3;   // own head

    const float2 q2 = ((const float2*)(g_q + (size_t)n * 64))[lane];
    const int p0 = g_roff[n];
    const int p1 = g_roff[n + 1];

    float2 a0 = make_float2(0.f, 0.f), a1 = a0, a2 = a0, a3 = a0;
    float z0 = 0.f;

#define GK_LOAD(kk, ww, sid)                                              \
    do {                                                                  \
        const float* _rp = g_kw + (size_t)(sid) * 96;                     \
        kk = ((const float2*)_rp)[lane];                                  \
        ww = ((const __half2*)(_rp + 64))[lane];                          \
    } while (0)

#define GK_CONSUME(kk, hw2)                                               \
    do {                                                                  \
        float prod = kk.x * q2.x + kk.y * q2.y;                           \
        prod += __shfl_xor_sync(0xffffffffu, prod, 4);                    \
        prod += __shfl_xor_sync(0xffffffffu, prod, 2);                    \
        prod += __shfl_xor_sync(0xffffffffu, prod, 1);                    \
        const float ew = __expf(prod);                                    \
        const float eA = __shfl_xor_sync(0xffffffffu, ew, 8);             \
        const float eB = __shfl_xor_sync(0xffffffffu, ew, 16);            \
        const float eC = __shfl_xor_sync(0xffffffffu, ew, 24);            \
        const float2 ww = __half22float2(hw2);                            \
        z0 += ew;                                                         \
        a0.x += ew * ww.x; a0.y += ew * ww.y;                             \
        a1.x += eA * ww.x; a1.y += eA * ww.y;                             \
        a2.x += eB * ww.x; a2.y += eB * ww.y;                             \
        a3.x += eC * ww.x; a3.y += eC * ww.y;                             \
    } while (0)

    if (p0 < p1) {
        float2 ka, kb;
        __half2 wa, wb;
        GK_LOAD(ka, wa, g_esrc[p0]);
        if (p0 + 1 < p1) GK_LOAD(kb, wb, g_esrc[p0 + 1]);

        int p = p0;
        for (; p + 1 < p1; p += 2) {
            float2 kn0 = ka, kn1 = kb;
            __half2 wn0 = wa, wn1 = wb;
            if (p + 2 < p1) GK_LOAD(kn0, wn0, g_esrc[p + 2]);
            if (p + 3 < p1) GK_LOAD(kn1, wn1, g_esrc[p + 3]);

            GK_CONSUME(ka, wa);
            GK_CONSUME(kb, wb);

            ka = kn0; wa = wn0; kb = kn1; wb = wn1;
        }
        if (p < p1) GK_CONSUME(ka, wa);
    }
#undef GK_LOAD
#undef GK_CONSUME

    // other heads' z from own-head lanes
    const float z1 = __shfl_xor_sync(0xffffffffu, z0, 8);
    const float z2 = __shfl_xor_sync(0xffffffffu, z0, 16);
    const float z3 = __shfl_xor_sync(0xffffffffu, z0, 24);

    const float i0 = (z0 > 0.f) ? 1.f / z0 : 0.f;
    const float i1 = (z1 > 0.f) ? 1.f / z1 : 0.f;
    const float i2 = (z2 > 0.f) ? 1.f / z2 : 0.f;
    const float i3 = (z3 > 0.f) ? 1.f / z3 : 0.f;

    const float2 bb = ((const float2*)b)[lane];   // features 2l, 2l+1
    float* op = out + (size_t)n * 256 + 2 * lane;

    *(float2*)(op + (size_t)(hh     ) * 64) = make_float2(a0.x * i0 + bb.x, a0.y * i0 + bb.y);
    *(float2*)(op + (size_t)(hh ^ 1) * 64) = make_float2(a1.x * i1 + bb.x, a1.y * i1 + bb.y);
    *(float2*)(op + (size_t)(hh ^ 2) * 64) = make_float2(a2.x * i2 + bb.x, a2.y * i2 + bb.y);
    *(float2*)(op + (size_t)(hh ^ 3) * 64) = make_float2(a3.x * i3 + bb.x, a3.y * i3 + bb.y);
}

// ---------------------------------------------------------------------------
extern "C" void kernel_launch(void* const* d_in, const int* in_sizes, int n_in,
                              void* d_out, int out_size)
{
    const float* h   = (const float*)d_in[0];
    const int*   src = (const int*)  d_in[1];
    const int*   dst = (const int*)  d_in[2];
    const float* Wk  = (const float*)d_in[3];
    const float* Wq  = (const float*)d_in[4];
    const float* Ww  = (const float*)d_in[5];
    const float* b   = (const float*)d_in[6];
    float*       out = (float*)d_out;

    const int N  = in_sizes[0] / 64;
    const int E  = in_sizes[1];
    const int nb = (N + 255) / 256;

    static void* cnt_ptr = nullptr;
    static cudaStream_t sideStream = nullptr;
    static cudaEvent_t  evFork = nullptr, evJoin = nullptr;
    if (cnt_ptr == nullptr) {
        cudaGetSymbolAddress(&cnt_ptr, g_cnt);
        cudaStreamCreateWithFlags(&sideStream, cudaStreamNonBlocking);
        cudaEventCreateWithFlags(&evFork, cudaEventDisableTiming);
        cudaEventCreateWithFlags(&evJoin, cudaEventDisableTiming);
    }

    // Fork: pure gemm (h,W only) overlaps the whole CSR chain (src,dst only).
    cudaEventRecord(evFork, 0);
    cudaStreamWaitEvent(sideStream, evFork, 0);
    gemm_mma_kernel<<<(N + 127) / 128, 192, 0, sideStream>>>(h, Wk, Wq, Ww, N);
    cudaEventRecord(evJoin, sideStream);

    cudaMemsetAsync(cnt_ptr, 0, (size_t)N * sizeof(int));
    hist_kernel<<<(E / 4 + 255) / 256, 256>>>(dst, E);
    scan1_kernel<<<nb, 256>>>(N);
    scan23_kernel<<<nb, 256>>>(N, E, nb);
    scatter_kernel<<<(E / 4 + 255) / 256, 256>>>(src, dst, E);

    cudaStreamWaitEvent(0, evJoin, 0);
    gather_kernel<<<(N + 1) / 2, 64>>>(b, out, N);
}